// round 13
// baseline (speedup 1.0000x reference)
#include <cuda_runtime.h>

#define N_NODES 100000
#define E_EDGES 1600000
#define IN_DIMC 128
#define HID 64
#define EMB 32

// ---------------- device scratch (no allocations allowed) ----------------
__device__ int   g_deg[N_NODES];
__device__ float g_dinv[N_NODES];
__device__ float g_hs  [(size_t)N_NODES * HID];  // (x@W1) * dinv[row]
__device__ float g_acc1[(size_t)N_NODES * HID];  // scatter accumulator L1
__device__ float g_zs  [(size_t)N_NODES * EMB];  // (h1@W2) * dinv[row]
__device__ float g_acc2[(size_t)N_NODES * EMB];  // scatter accumulator L2

// one-instruction 16B global f32 reduction (sm_90+)
__device__ __forceinline__ void red_add_v4(float* addr, float4 v) {
    asm volatile("red.global.add.v4.f32 [%0], {%1, %2, %3, %4};"
                 :: "l"(addr), "f"(v.x), "f"(v.y), "f"(v.z), "f"(v.w)
                 : "memory");
}

__device__ __forceinline__ int clampN(int v) {
    return ((unsigned)v >= N_NODES) ? 0 : v;   // defensive: rel_err not crash
}

// packed fp32x2 helpers (sm_100+)
__device__ __forceinline__ unsigned long long dupf(float a) {
    unsigned long long r;
    asm("mov.b64 %0, {%1, %1};" : "=l"(r) : "f"(a));
    return r;
}
__device__ __forceinline__ void fma2(unsigned long long& d,
                                     unsigned long long a, unsigned long long b) {
    asm("fma.rn.f32x2 %0, %1, %2, %0;" : "+l"(d) : "l"(a), "l"(b));
}
__device__ __forceinline__ float2 unpk(unsigned long long v) {
    float lo, hi;
    asm("mov.b64 {%0, %1}, %2;" : "=f"(lo), "=f"(hi) : "l"(v));
    return make_float2(lo, hi);
}

// tf32 helpers
__device__ __forceinline__ unsigned tf32_of(float f) {
    unsigned r;
    asm("cvt.rna.tf32.f32 %0, %1;" : "=r"(r) : "f"(f));
    return r;
}
__device__ __forceinline__ void split_tf32(float f, unsigned& hi, unsigned& lo) {
    hi = tf32_of(f);
    lo = tf32_of(f - __uint_as_float(hi));
}

// tf32 tensor-core mma: D(16x8) += A(16x8) * B(8x8), A row-major, B col-major
__device__ __forceinline__ void mma_tf32(float* c,
                                         unsigned a0, unsigned a1, unsigned a2, unsigned a3,
                                         unsigned b0, unsigned b1) {
    asm volatile(
        "mma.sync.aligned.m16n8k8.row.col.f32.tf32.tf32.f32 "
        "{%0,%1,%2,%3}, {%4,%5,%6,%7}, {%8,%9}, {%0,%1,%2,%3};"
        : "+f"(c[0]), "+f"(c[1]), "+f"(c[2]), "+f"(c[3])
        : "r"(a0), "r"(a1), "r"(a2), "r"(a3), "r"(b0), "r"(b1));
}

// ---------------- degree / dinv prep ----------------
__global__ void k_init_deg() {
    int i = blockIdx.x * blockDim.x + threadIdx.x;
    if (i < N_NODES) g_deg[i] = 1;  // self-loop
}

__global__ void k_edges(const int* __restrict__ ei) {
    int i = blockIdx.x * blockDim.x + threadIdx.x;
    if (i < E_EDGES) {
        int t = clampN(ei[E_EDGES + i]);
        atomicAdd(&g_deg[t], 1);
    }
}

__global__ void k_dinv() {
    int i = blockIdx.x * blockDim.x + threadIdx.x;
    if (i < N_NODES) g_dinv[i] = rsqrtf((float)g_deg[i]);
}

// ---------------- GEMM1 (3xTF32 tensor cores): hs = (x @ W1) * dinv; acc1 = hs ---
// tile 128 rows x 64 cols, K=128 resident. 8 warps = 4 row-groups x 2 col-groups;
// warp covers 32 rows (2 m16 frags) x 32 cols (4 n8 frags). acc = ah*bh+ah*bl+al*bh.
__global__ void k_gemm1(const float* __restrict__ x, const float* __restrict__ W1) {
    __shared__ float    xs [128][132];  // [row][k]; bank (4r+k)%32 -> conflict-free
    __shared__ unsigned wsh[128][72];   // tf32 hi of W1, [k][n]; bank (8k+n)%32
    __shared__ unsigned wsl[128][72];   // tf32 lo of W1
    int row0 = blockIdx.x * 128;
    int tid  = threadIdx.x;             // 256
    int warp = tid >> 5, lane = tid & 31;
    int warp_r = warp >> 1, warp_c = warp & 1;

    // stage x tile: 128 rows x 32 float4 = 4096 float4, 16 per thread (coalesced)
    #pragma unroll
    for (int i = 0; i < 16; i++) {
        int lin = tid + i * 256;
        int r = lin >> 5, f4 = lin & 31;
        float4 v = make_float4(0.f, 0.f, 0.f, 0.f);
        int row = row0 + r;
        if (row < N_NODES)
            v = *(const float4*)&x[(size_t)row * IN_DIMC + f4 * 4];
        *(float4*)&xs[r][f4 * 4] = v;
    }
    // stage + split W1: 128 k x 16 float4 = 2048 float4, 8 per thread
    #pragma unroll
    for (int i = 0; i < 8; i++) {
        int lin = tid + i * 256;
        int k = lin >> 4, c4 = lin & 15;
        float4 v = *(const float4*)&W1[(size_t)k * HID + c4 * 4];
        unsigned h0, l0, h1, l1, h2, l2, h3, l3;
        split_tf32(v.x, h0, l0); split_tf32(v.y, h1, l1);
        split_tf32(v.z, h2, l2); split_tf32(v.w, h3, l3);
        wsh[k][c4 * 4 + 0] = h0; wsh[k][c4 * 4 + 1] = h1;
        wsh[k][c4 * 4 + 2] = h2; wsh[k][c4 * 4 + 3] = h3;
        wsl[k][c4 * 4 + 0] = l0; wsl[k][c4 * 4 + 1] = l1;
        wsl[k][c4 * 4 + 2] = l2; wsl[k][c4 * 4 + 3] = l3;
    }
    __syncthreads();

    float acc[2][4][4] = {};
    int q  = lane >> 2;        // 0..7
    int kc = lane & 3;         // 0..3

    #pragma unroll 4
    for (int k0 = 0; k0 < IN_DIMC; k0 += 8) {
        unsigned ah[2][4], al[2][4];
        #pragma unroll
        for (int m = 0; m < 2; m++) {
            int r0 = warp_r * 32 + m * 16 + q;
            split_tf32(xs[r0    ][k0 + kc    ], ah[m][0], al[m][0]);
            split_tf32(xs[r0 + 8][k0 + kc    ], ah[m][1], al[m][1]);
            split_tf32(xs[r0    ][k0 + kc + 4], ah[m][2], al[m][2]);
            split_tf32(xs[r0 + 8][k0 + kc + 4], ah[m][3], al[m][3]);
        }
        #pragma unroll
        for (int j = 0; j < 4; j++) {
            int col = warp_c * 32 + j * 8 + q;
            unsigned bh0 = wsh[k0 + kc    ][col];
            unsigned bh1 = wsh[k0 + kc + 4][col];
            unsigned bl0 = wsl[k0 + kc    ][col];
            unsigned bl1 = wsl[k0 + kc + 4][col];
            #pragma unroll
            for (int m = 0; m < 2; m++) {
                mma_tf32(acc[m][j], ah[m][0], ah[m][1], ah[m][2], ah[m][3], bh0, bh1);
                mma_tf32(acc[m][j], ah[m][0], ah[m][1], ah[m][2], ah[m][3], bl0, bl1);
                mma_tf32(acc[m][j], al[m][0], al[m][1], al[m][2], al[m][3], bh0, bh1);
            }
        }
    }

    // epilogue: lane (q,kc) of (m,j) tile holds rows (base+q, base+q+8),
    // cols warp_c*32 + j*8 + 2*kc + {0,1}
    #pragma unroll
    for (int m = 0; m < 2; m++) {
        int rr0 = row0 + warp_r * 32 + m * 16 + q;
        int rr1 = rr0 + 8;
        float d0 = (rr0 < N_NODES) ? g_dinv[rr0] : 0.f;
        float d1 = (rr1 < N_NODES) ? g_dinv[rr1] : 0.f;
        #pragma unroll
        for (int j = 0; j < 4; j++) {
            int col = warp_c * 32 + j * 8 + 2 * kc;
            if (rr0 < N_NODES) {
                float2 v = make_float2(acc[m][j][0] * d0, acc[m][j][1] * d0);
                size_t idx = (size_t)rr0 * HID + col;
                *(float2*)&g_hs[idx]   = v;
                *(float2*)&g_acc1[idx] = v;   // self-loop contribution
            }
            if (rr1 < N_NODES) {
                float2 v = make_float2(acc[m][j][2] * d1, acc[m][j][3] * d1);
                size_t idx = (size_t)rr1 * HID + col;
                *(float2*)&g_hs[idx]   = v;
                *(float2*)&g_acc1[idx] = v;
            }
        }
    }
}

// ---------------- scatter layer 1: acc1[tgt] += hs[src], 64 dims ----------------
__global__ void k_scatter1(const int* __restrict__ ei) {
    int tid = blockIdx.x * blockDim.x + threadIdx.x;   // E*16
    int e = tid >> 4, c = tid & 15;
    int s = clampN(__ldg(&ei[e]));
    int t = clampN(__ldg(&ei[E_EDGES + e]));
    float4 v = *(const float4*)&g_hs[(size_t)s * HID + c * 4];
    red_add_v4(&g_acc1[(size_t)t * HID + c * 4], v);
}

// ---------------- GEMM2: zs = (relu(acc1*dinv+b1) @ W2) * dinv[row]; acc2 = zs ----
// block: 64 rows x 32 cols, threads (8,16), 4x4 micro-tile, K=64 — f32x2 math
__global__ void k_gemm2(const float* __restrict__ W2, const float* __restrict__ b1) {
    __shared__ float hsm[64][68];
    __shared__ float wsm[64][36];
    int row0 = blockIdx.x * 64;
    int tx = threadIdx.x, ty = threadIdx.y;
    int tid = ty * 8 + tx;                    // 128 threads
    unsigned long long acc[4][2] = {};

    #pragma unroll
    for (int i = 0; i < 8; i++) {
        int lin = tid + i * 128;
        int r = lin >> 4, k4 = lin & 15;
        float4 v = make_float4(0.f, 0.f, 0.f, 0.f);
        int row = row0 + r;
        if (row < N_NODES) {
            float d = g_dinv[row];
            float4 a  = *(const float4*)&g_acc1[(size_t)row * HID + k4 * 4];
            float4 bb = *(const float4*)&b1[k4 * 4];
            v.x = fmaxf(a.x * d + bb.x, 0.f);
            v.y = fmaxf(a.y * d + bb.y, 0.f);
            v.z = fmaxf(a.z * d + bb.z, 0.f);
            v.w = fmaxf(a.w * d + bb.w, 0.f);
        }
        *(float4*)&hsm[r][k4 * 4] = v;
    }
    #pragma unroll
    for (int i = 0; i < 4; i++) {
        int lin = tid + i * 128;
        int k = lin >> 3, c4 = lin & 7;
        float4 v = *(const float4*)&W2[(size_t)k * EMB + c4 * 4];
        *(float4*)&wsm[k][c4 * 4] = v;
    }
    __syncthreads();
    #pragma unroll 8
    for (int kk = 0; kk < 64; kk++) {
        ulonglong2 b = *(const ulonglong2*)&wsm[kk][tx * 4];   // LDS.128
        #pragma unroll
        for (int i = 0; i < 4; i++) {
            unsigned long long aa = dupf(hsm[ty * 4 + i][kk]);
            fma2(acc[i][0], aa, b.x);
            fma2(acc[i][1], aa, b.y);
        }
    }
    #pragma unroll
    for (int i = 0; i < 4; i++) {
        int row = row0 + ty * 4 + i;
        if (row < N_NODES) {
            float d = g_dinv[row];
            float2 p0 = unpk(acc[i][0]);
            float2 p1 = unpk(acc[i][1]);
            float4 v = make_float4(p0.x * d, p0.y * d, p1.x * d, p1.y * d);
            size_t idx = (size_t)row * EMB + tx * 4;
            *(float4*)&g_zs[idx]   = v;
            *(float4*)&g_acc2[idx] = v;
        }
    }
}

// ---------------- scatter layer 2: acc2[tgt] += zs[src], 32 dims ----------------
__global__ void k_scatter2(const int* __restrict__ ei) {
    int tid = blockIdx.x * blockDim.x + threadIdx.x;   // E*8
    int e = tid >> 3, c = tid & 7;
    int s = clampN(__ldg(&ei[e]));
    int t = clampN(__ldg(&ei[E_EDGES + e]));
    float4 v = *(const float4*)&g_zs[(size_t)s * EMB + c * 4];
    red_add_v4(&g_acc2[(size_t)t * EMB + c * 4], v);
}

// ---------------- final z: z = dinv*acc2 + b2 -> d_out ----------------
__global__ void k_z(const float* __restrict__ b2, float* __restrict__ z_out) {
    int idx = blockIdx.x * blockDim.x + threadIdx.x;   // N*8 float4s
    int row = idx >> 3, c = idx & 7;
    float d = g_dinv[row];
    float4 a = *(const float4*)&g_acc2[(size_t)idx * 4];
    float4 bb = *(const float4*)&b2[c * 4];
    float4 o = make_float4(a.x * d + bb.x, a.y * d + bb.y, a.z * d + bb.z, a.w * d + bb.w);
    *(float4*)&z_out[(size_t)idx * 4] = o;
}

// ---------------- decode: recon[e] = dot(z[src], z[tgt]) ----------------
__global__ void k_decode(const int* __restrict__ ei,
                         const float* __restrict__ z, float* __restrict__ recon) {
    int tid = blockIdx.x * blockDim.x + threadIdx.x;   // E*8
    int e = tid >> 3, c = tid & 7;
    int s = clampN(__ldg(&ei[e]));
    int t = clampN(__ldg(&ei[E_EDGES + e]));
    float4 a = *(const float4*)&z[(size_t)s * EMB + c * 4];
    float4 b = *(const float4*)&z[(size_t)t * EMB + c * 4];
    float p = a.x * b.x + a.y * b.y + a.z * b.z + a.w * b.w;
    p += __shfl_down_sync(0xffffffffu, p, 4);
    p += __shfl_down_sync(0xffffffffu, p, 2);
    p += __shfl_down_sync(0xffffffffu, p, 1);
    if (c == 0) recon[e] = p;
}

// ---------------- launch ----------------
extern "C" void kernel_launch(void* const* d_in, const int* in_sizes, int n_in,
                              void* d_out, int out_size) {
    const float* x  = (const float*)d_in[0];
    const float* W1 = (const float*)d_in[1];
    const float* b1 = (const float*)d_in[2];
    const float* W2 = (const float*)d_in[3];
    const float* b2 = (const float*)d_in[4];
    const int*   ei = (const int*)d_in[5];
    float* z_out = (float*)d_out;                          // N*EMB
    float* recon = (float*)d_out + (size_t)N_NODES * EMB;  // E

    k_init_deg<<<(N_NODES + 255) / 256, 256>>>();
    k_edges<<<E_EDGES / 256, 256>>>(ei);
    k_dinv<<<(N_NODES + 255) / 256, 256>>>();

    k_gemm1<<<(N_NODES + 127) / 128, 256>>>(x, W1);
    k_scatter1<<<(E_EDGES * 16) / 256, 256>>>(ei);

    k_gemm2<<<(N_NODES + 63) / 64, dim3(8, 16)>>>(W2, b1);
    k_scatter2<<<(E_EDGES * 8) / 256, 256>>>(ei);
    k_z<<<(N_NODES * 8) / 256, 256>>>(b2, z_out);

    k_decode<<<(E_EDGES * 8) / 256, 256>>>(ei, z_out, recon);
}

// round 14
// speedup vs baseline: 1.0244x; 1.0244x over previous
#include <cuda_runtime.h>

#define N_NODES 100000
#define E_EDGES 1600000
#define IN_DIMC 128
#define HID 64
#define EMB 32

// ---------------- device scratch (no allocations allowed) ----------------
__device__ int   g_deg[N_NODES];
__device__ float g_hs  [(size_t)N_NODES * HID];  // (x@W1) * dinv[row]
__device__ float g_acc1[(size_t)N_NODES * HID];  // scatter accumulator L1
__device__ float g_zs  [(size_t)N_NODES * EMB];  // (h1@W2) * dinv[row]
__device__ float g_acc2[(size_t)N_NODES * EMB];  // scatter accumulator L2

// one-instruction 16B global f32 reduction (sm_90+)
__device__ __forceinline__ void red_add_v4(float* addr, float4 v) {
    asm volatile("red.global.add.v4.f32 [%0], {%1, %2, %3, %4};"
                 :: "l"(addr), "f"(v.x), "f"(v.y), "f"(v.z), "f"(v.w)
                 : "memory");
}

__device__ __forceinline__ int clampN(int v) {
    return ((unsigned)v >= N_NODES) ? 0 : v;   // defensive: rel_err not crash
}

// packed fp32x2 helpers (sm_100+)
__device__ __forceinline__ unsigned long long dupf(float a) {
    unsigned long long r;
    asm("mov.b64 %0, {%1, %1};" : "=l"(r) : "f"(a));
    return r;
}
__device__ __forceinline__ void fma2(unsigned long long& d,
                                     unsigned long long a, unsigned long long b) {
    asm("fma.rn.f32x2 %0, %1, %2, %0;" : "+l"(d) : "l"(a), "l"(b));
}
__device__ __forceinline__ float2 unpk(unsigned long long v) {
    float lo, hi;
    asm("mov.b64 {%0, %1}, %2;" : "=f"(lo), "=f"(hi) : "l"(v));
    return make_float2(lo, hi);
}

// tf32 helpers
__device__ __forceinline__ unsigned tf32_of(float f) {
    unsigned r;
    asm("cvt.rna.tf32.f32 %0, %1;" : "=r"(r) : "f"(f));
    return r;
}
__device__ __forceinline__ void split_tf32(float f, unsigned& hi, unsigned& lo) {
    hi = tf32_of(f);
    lo = tf32_of(f - __uint_as_float(hi));
}

// tf32 tensor-core mma: D(16x8) += A(16x8) * B(8x8), A row-major, B col-major
__device__ __forceinline__ void mma_tf32(float* c,
                                         unsigned a0, unsigned a1, unsigned a2, unsigned a3,
                                         unsigned b0, unsigned b1) {
    asm volatile(
        "mma.sync.aligned.m16n8k8.row.col.f32.tf32.tf32.f32 "
        "{%0,%1,%2,%3}, {%4,%5,%6,%7}, {%8,%9}, {%0,%1,%2,%3};"
        : "+f"(c[0]), "+f"(c[1]), "+f"(c[2]), "+f"(c[3])
        : "r"(a0), "r"(a1), "r"(a2), "r"(a3), "r"(b0), "r"(b1));
}

// ---------------- degree prep ----------------
__global__ void k_init_deg() {
    int i = blockIdx.x * blockDim.x + threadIdx.x;
    if (i < N_NODES) g_deg[i] = 1;  // self-loop
}

__global__ void k_edges(const int* __restrict__ ei) {
    int i = blockIdx.x * blockDim.x + threadIdx.x;
    if (i < E_EDGES) {
        int t = clampN(ei[E_EDGES + i]);
        atomicAdd(&g_deg[t], 1);
    }
}

// ---------------- GEMM1 (3xTF32 tensor cores): hs = (x @ W1) * dinv; acc1 = hs ---
// tile 64 rows x 64 cols, K=128 resident, smem 105KB -> 2 CTAs/SM.
// 8 warps = 4 row-groups x 2 col-groups; warp = 16 rows (1 m16) x 32 cols (4 n8).
__global__ void __launch_bounds__(256, 2)
k_gemm1(const float* __restrict__ x, const float* __restrict__ W1) {
    __shared__ float    xs [64][132];   // [row][k]; bank (4r+k)%32 -> conflict-free
    __shared__ unsigned wsh[128][72];   // tf32 hi of W1, [k][n]; bank (8k+n)%32
    __shared__ unsigned wsl[128][72];   // tf32 lo of W1
    int row0 = blockIdx.x * 64;
    int tid  = threadIdx.x;             // 256
    int warp = tid >> 5, lane = tid & 31;
    int warp_r = warp >> 1, warp_c = warp & 1;

    // stage x tile: 64 rows x 32 float4 = 2048 float4, 8 per thread (coalesced)
    #pragma unroll
    for (int i = 0; i < 8; i++) {
        int lin = tid + i * 256;
        int r = lin >> 5, f4 = lin & 31;
        float4 v = make_float4(0.f, 0.f, 0.f, 0.f);
        int row = row0 + r;
        if (row < N_NODES)
            v = *(const float4*)&x[(size_t)row * IN_DIMC + f4 * 4];
        *(float4*)&xs[r][f4 * 4] = v;
    }
    // stage + split W1: 128 k x 16 float4 = 2048 float4, 8 per thread
    #pragma unroll
    for (int i = 0; i < 8; i++) {
        int lin = tid + i * 256;
        int k = lin >> 4, c4 = lin & 15;
        float4 v = *(const float4*)&W1[(size_t)k * HID + c4 * 4];
        unsigned h0, l0, h1, l1, h2, l2, h3, l3;
        split_tf32(v.x, h0, l0); split_tf32(v.y, h1, l1);
        split_tf32(v.z, h2, l2); split_tf32(v.w, h3, l3);
        wsh[k][c4 * 4 + 0] = h0; wsh[k][c4 * 4 + 1] = h1;
        wsh[k][c4 * 4 + 2] = h2; wsh[k][c4 * 4 + 3] = h3;
        wsl[k][c4 * 4 + 0] = l0; wsl[k][c4 * 4 + 1] = l1;
        wsl[k][c4 * 4 + 2] = l2; wsl[k][c4 * 4 + 3] = l3;
    }
    __syncthreads();

    float acc[4][4] = {};
    int q  = lane >> 2;        // 0..7
    int kc = lane & 3;         // 0..3
    int r0 = warp_r * 16 + q;  // fragment rows r0, r0+8

    #pragma unroll 4
    for (int k0 = 0; k0 < IN_DIMC; k0 += 8) {
        unsigned ah[4], al[4];
        split_tf32(xs[r0    ][k0 + kc    ], ah[0], al[0]);
        split_tf32(xs[r0 + 8][k0 + kc    ], ah[1], al[1]);
        split_tf32(xs[r0    ][k0 + kc + 4], ah[2], al[2]);
        split_tf32(xs[r0 + 8][k0 + kc + 4], ah[3], al[3]);
        #pragma unroll
        for (int j = 0; j < 4; j++) {
            int col = warp_c * 32 + j * 8 + q;
            unsigned bh0 = wsh[k0 + kc    ][col];
            unsigned bh1 = wsh[k0 + kc + 4][col];
            unsigned bl0 = wsl[k0 + kc    ][col];
            unsigned bl1 = wsl[k0 + kc + 4][col];
            mma_tf32(acc[j], ah[0], ah[1], ah[2], ah[3], bh0, bh1);
            mma_tf32(acc[j], ah[0], ah[1], ah[2], ah[3], bl0, bl1);
            mma_tf32(acc[j], al[0], al[1], al[2], al[3], bh0, bh1);
        }
    }

    // epilogue: lane (q,kc) of tile j holds rows (rr0, rr0+8), cols warp_c*32+j*8+2kc+{0,1}
    int rr0 = row0 + r0, rr1 = rr0 + 8;
    float d0 = (rr0 < N_NODES) ? rsqrtf((float)g_deg[rr0]) : 0.f;
    float d1 = (rr1 < N_NODES) ? rsqrtf((float)g_deg[rr1]) : 0.f;
    #pragma unroll
    for (int j = 0; j < 4; j++) {
        int col = warp_c * 32 + j * 8 + 2 * kc;
        if (rr0 < N_NODES) {
            float2 v = make_float2(acc[j][0] * d0, acc[j][1] * d0);
            size_t idx = (size_t)rr0 * HID + col;
            *(float2*)&g_hs[idx]   = v;
            *(float2*)&g_acc1[idx] = v;   // self-loop contribution
        }
        if (rr1 < N_NODES) {
            float2 v = make_float2(acc[j][2] * d1, acc[j][3] * d1);
            size_t idx = (size_t)rr1 * HID + col;
            *(float2*)&g_hs[idx]   = v;
            *(float2*)&g_acc1[idx] = v;
        }
    }
}

// ---------------- scatter layer 1: acc1[tgt] += hs[src], 64 dims ----------------
__global__ void k_scatter1(const int* __restrict__ ei) {
    int tid = blockIdx.x * blockDim.x + threadIdx.x;   // E*16
    int e = tid >> 4, c = tid & 15;
    int s = clampN(__ldg(&ei[e]));
    int t = clampN(__ldg(&ei[E_EDGES + e]));
    float4 v = *(const float4*)&g_hs[(size_t)s * HID + c * 4];
    red_add_v4(&g_acc1[(size_t)t * HID + c * 4], v);
}

// ---------------- GEMM2: zs = (relu(acc1*dinv+b1) @ W2) * dinv[row]; acc2 = zs ----
// block: 64 rows x 32 cols, threads (8,16), 4x4 micro-tile, K=64 — f32x2 math
__global__ void k_gemm2(const float* __restrict__ W2, const float* __restrict__ b1) {
    __shared__ float hsm[64][68];
    __shared__ float wsm[64][36];
    int row0 = blockIdx.x * 64;
    int tx = threadIdx.x, ty = threadIdx.y;
    int tid = ty * 8 + tx;                    // 128 threads
    unsigned long long acc[4][2] = {};

    #pragma unroll
    for (int i = 0; i < 8; i++) {
        int lin = tid + i * 128;
        int r = lin >> 4, k4 = lin & 15;
        float4 v = make_float4(0.f, 0.f, 0.f, 0.f);
        int row = row0 + r;
        if (row < N_NODES) {
            float d = rsqrtf((float)g_deg[row]);
            float4 a  = *(const float4*)&g_acc1[(size_t)row * HID + k4 * 4];
            float4 bb = *(const float4*)&b1[k4 * 4];
            v.x = fmaxf(a.x * d + bb.x, 0.f);
            v.y = fmaxf(a.y * d + bb.y, 0.f);
            v.z = fmaxf(a.z * d + bb.z, 0.f);
            v.w = fmaxf(a.w * d + bb.w, 0.f);
        }
        *(float4*)&hsm[r][k4 * 4] = v;
    }
    #pragma unroll
    for (int i = 0; i < 4; i++) {
        int lin = tid + i * 128;
        int k = lin >> 3, c4 = lin & 7;
        float4 v = *(const float4*)&W2[(size_t)k * EMB + c4 * 4];
        *(float4*)&wsm[k][c4 * 4] = v;
    }
    __syncthreads();
    #pragma unroll 8
    for (int kk = 0; kk < 64; kk++) {
        ulonglong2 b = *(const ulonglong2*)&wsm[kk][tx * 4];   // LDS.128
        #pragma unroll
        for (int i = 0; i < 4; i++) {
            unsigned long long aa = dupf(hsm[ty * 4 + i][kk]);
            fma2(acc[i][0], aa, b.x);
            fma2(acc[i][1], aa, b.y);
        }
    }
    #pragma unroll
    for (int i = 0; i < 4; i++) {
        int row = row0 + ty * 4 + i;
        if (row < N_NODES) {
            float d = rsqrtf((float)g_deg[row]);
            float2 p0 = unpk(acc[i][0]);
            float2 p1 = unpk(acc[i][1]);
            float4 v = make_float4(p0.x * d, p0.y * d, p1.x * d, p1.y * d);
            size_t idx = (size_t)row * EMB + tx * 4;
            *(float4*)&g_zs[idx]   = v;
            *(float4*)&g_acc2[idx] = v;
        }
    }
}

// ---------------- scatter layer 2: acc2[tgt] += zs[src], 32 dims ----------------
__global__ void k_scatter2(const int* __restrict__ ei) {
    int tid = blockIdx.x * blockDim.x + threadIdx.x;   // E*8
    int e = tid >> 3, c = tid & 7;
    int s = clampN(__ldg(&ei[e]));
    int t = clampN(__ldg(&ei[E_EDGES + e]));
    float4 v = *(const float4*)&g_zs[(size_t)s * EMB + c * 4];
    red_add_v4(&g_acc2[(size_t)t * EMB + c * 4], v);
}

// ---------------- final z: z = dinv*acc2 + b2 -> d_out ----------------
__global__ void k_z(const float* __restrict__ b2, float* __restrict__ z_out) {
    int idx = blockIdx.x * blockDim.x + threadIdx.x;   // N*8 float4s
    int row = idx >> 3, c = idx & 7;
    float d = rsqrtf((float)g_deg[row]);
    float4 a = *(const float4*)&g_acc2[(size_t)idx * 4];
    float4 bb = *(const float4*)&b2[c * 4];
    float4 o = make_float4(a.x * d + bb.x, a.y * d + bb.y, a.z * d + bb.z, a.w * d + bb.w);
    *(float4*)&z_out[(size_t)idx * 4] = o;
}

// ---------------- decode: recon[e] = dot(z[src], z[tgt]) ----------------
__global__ void k_decode(const int* __restrict__ ei,
                         const float* __restrict__ z, float* __restrict__ recon) {
    int tid = blockIdx.x * blockDim.x + threadIdx.x;   // E*8
    int e = tid >> 3, c = tid & 7;
    int s = clampN(__ldg(&ei[e]));
    int t = clampN(__ldg(&ei[E_EDGES + e]));
    float4 a = *(const float4*)&z[(size_t)s * EMB + c * 4];
    float4 b = *(const float4*)&z[(size_t)t * EMB + c * 4];
    float p = a.x * b.x + a.y * b.y + a.z * b.z + a.w * b.w;
    p += __shfl_down_sync(0xffffffffu, p, 4);
    p += __shfl_down_sync(0xffffffffu, p, 2);
    p += __shfl_down_sync(0xffffffffu, p, 1);
    if (c == 0) recon[e] = p;
}

// ---------------- launch ----------------
extern "C" void kernel_launch(void* const* d_in, const int* in_sizes, int n_in,
                              void* d_out, int out_size) {
    const float* x  = (const float*)d_in[0];
    const float* W1 = (const float*)d_in[1];
    const float* b1 = (const float*)d_in[2];
    const float* W2 = (const float*)d_in[3];
    const float* b2 = (const float*)d_in[4];
    const int*   ei = (const int*)d_in[5];
    float* z_out = (float*)d_out;                          // N*EMB
    float* recon = (float*)d_out + (size_t)N_NODES * EMB;  // E

    k_init_deg<<<(N_NODES + 255) / 256, 256>>>();
    k_edges<<<E_EDGES / 256, 256>>>(ei);

    k_gemm1<<<(N_NODES + 63) / 64, 256>>>(x, W1);
    k_scatter1<<<(E_EDGES * 16) / 256, 256>>>(ei);

    k_gemm2<<<(N_NODES + 63) / 64, dim3(8, 16)>>>(W2, b1);
    k_scatter2<<<(E_EDGES * 8) / 256, 256>>>(ei);
    k_z<<<(N_NODES * 8) / 256, 256>>>(b2, z_out);

    k_decode<<<(E_EDGES * 8) / 256, 256>>>(ei, z_out, recon);
}

// round 15
// speedup vs baseline: 1.0312x; 1.0066x over previous
#include <cuda_runtime.h>

#define N_NODES 100000
#define E_EDGES 1600000
#define IN_DIMC 128
#define HID 64
#define EMB 32

// ---------------- device scratch (no allocations allowed) ----------------
__device__ int   g_deg[N_NODES];
__device__ float g_hs  [(size_t)N_NODES * HID];  // (x@W1) * dinv[row]
__device__ float g_acc1[(size_t)N_NODES * HID];  // scatter accumulator L1
__device__ float g_zs  [(size_t)N_NODES * EMB];  // (h1@W2) * dinv[row]
__device__ float g_acc2[(size_t)N_NODES * EMB];  // scatter accumulator L2

// one-instruction 16B global f32 reduction (sm_90+)
__device__ __forceinline__ void red_add_v4(float* addr, float4 v) {
    asm volatile("red.global.add.v4.f32 [%0], {%1, %2, %3, %4};"
                 :: "l"(addr), "f"(v.x), "f"(v.y), "f"(v.z), "f"(v.w)
                 : "memory");
}

__device__ __forceinline__ int clampN(int v) {
    return ((unsigned)v >= N_NODES) ? 0 : v;   // defensive: rel_err not crash
}

// tf32 helpers
__device__ __forceinline__ unsigned tf32_of(float f) {
    unsigned r;
    asm("cvt.rna.tf32.f32 %0, %1;" : "=r"(r) : "f"(f));
    return r;
}
__device__ __forceinline__ void split_tf32(float f, unsigned& hi, unsigned& lo) {
    hi = tf32_of(f);
    lo = tf32_of(f - __uint_as_float(hi));
}

// tf32 tensor-core mma: D(16x8) += A(16x8) * B(8x8), A row-major, B col-major
__device__ __forceinline__ void mma_tf32(float* c,
                                         unsigned a0, unsigned a1, unsigned a2, unsigned a3,
                                         unsigned b0, unsigned b1) {
    asm volatile(
        "mma.sync.aligned.m16n8k8.row.col.f32.tf32.tf32.f32 "
        "{%0,%1,%2,%3}, {%4,%5,%6,%7}, {%8,%9}, {%0,%1,%2,%3};"
        : "+f"(c[0]), "+f"(c[1]), "+f"(c[2]), "+f"(c[3])
        : "r"(a0), "r"(a1), "r"(a2), "r"(a3), "r"(b0), "r"(b1));
}

// ---------------- degree prep ----------------
__global__ void k_init_deg() {
    int i = blockIdx.x * blockDim.x + threadIdx.x;
    if (i < N_NODES) g_deg[i] = 1;  // self-loop
}

__global__ void k_edges(const int* __restrict__ ei) {
    int i = blockIdx.x * blockDim.x + threadIdx.x;
    if (i < E_EDGES) {
        int t = clampN(ei[E_EDGES + i]);
        atomicAdd(&g_deg[t], 1);
    }
}

// ---------------- GEMM1 (3xTF32 tensor cores): hs = (x @ W1) * dinv; acc1 = hs ---
// tile 64 rows x 64 cols, K=128 resident, smem 105KB -> 2 CTAs/SM.
// 8 warps = 4 row-groups x 2 col-groups; warp = 16 rows (1 m16) x 32 cols (4 n8).
__global__ void __launch_bounds__(256, 2)
k_gemm1(const float* __restrict__ x, const float* __restrict__ W1) {
    __shared__ float    xs [64][132];   // [row][k]; bank (4r+k)%32 -> conflict-free
    __shared__ unsigned wsh[128][72];   // tf32 hi of W1, [k][n]; bank (8k+n)%32
    __shared__ unsigned wsl[128][72];   // tf32 lo of W1
    int row0 = blockIdx.x * 64;
    int tid  = threadIdx.x;             // 256
    int warp = tid >> 5, lane = tid & 31;
    int warp_r = warp >> 1, warp_c = warp & 1;

    // stage x tile: 64 rows x 32 float4 = 2048 float4, 8 per thread (coalesced)
    #pragma unroll
    for (int i = 0; i < 8; i++) {
        int lin = tid + i * 256;
        int r = lin >> 5, f4 = lin & 31;
        float4 v = make_float4(0.f, 0.f, 0.f, 0.f);
        int row = row0 + r;
        if (row < N_NODES)
            v = *(const float4*)&x[(size_t)row * IN_DIMC + f4 * 4];
        *(float4*)&xs[r][f4 * 4] = v;
    }
    // stage + split W1: 128 k x 16 float4 = 2048 float4, 8 per thread
    #pragma unroll
    for (int i = 0; i < 8; i++) {
        int lin = tid + i * 256;
        int k = lin >> 4, c4 = lin & 15;
        float4 v = *(const float4*)&W1[(size_t)k * HID + c4 * 4];
        unsigned h0, l0, h1, l1, h2, l2, h3, l3;
        split_tf32(v.x, h0, l0); split_tf32(v.y, h1, l1);
        split_tf32(v.z, h2, l2); split_tf32(v.w, h3, l3);
        wsh[k][c4 * 4 + 0] = h0; wsh[k][c4 * 4 + 1] = h1;
        wsh[k][c4 * 4 + 2] = h2; wsh[k][c4 * 4 + 3] = h3;
        wsl[k][c4 * 4 + 0] = l0; wsl[k][c4 * 4 + 1] = l1;
        wsl[k][c4 * 4 + 2] = l2; wsl[k][c4 * 4 + 3] = l3;
    }
    __syncthreads();

    float acc[4][4] = {};
    int q  = lane >> 2;        // 0..7
    int kc = lane & 3;         // 0..3
    int r0 = warp_r * 16 + q;  // fragment rows r0, r0+8

    #pragma unroll 4
    for (int k0 = 0; k0 < IN_DIMC; k0 += 8) {
        unsigned ah[4], al[4];
        split_tf32(xs[r0    ][k0 + kc    ], ah[0], al[0]);
        split_tf32(xs[r0 + 8][k0 + kc    ], ah[1], al[1]);
        split_tf32(xs[r0    ][k0 + kc + 4], ah[2], al[2]);
        split_tf32(xs[r0 + 8][k0 + kc + 4], ah[3], al[3]);
        #pragma unroll
        for (int j = 0; j < 4; j++) {
            int col = warp_c * 32 + j * 8 + q;
            unsigned bh0 = wsh[k0 + kc    ][col];
            unsigned bh1 = wsh[k0 + kc + 4][col];
            unsigned bl0 = wsl[k0 + kc    ][col];
            unsigned bl1 = wsl[k0 + kc + 4][col];
            mma_tf32(acc[j], ah[0], ah[1], ah[2], ah[3], bh0, bh1);
            mma_tf32(acc[j], ah[0], ah[1], ah[2], ah[3], bl0, bl1);
            mma_tf32(acc[j], al[0], al[1], al[2], al[3], bh0, bh1);
        }
    }

    // epilogue: lane (q,kc) of tile j holds rows (rr0, rr0+8), cols warp_c*32+j*8+2kc+{0,1}
    int rr0 = row0 + r0, rr1 = rr0 + 8;
    float d0 = (rr0 < N_NODES) ? rsqrtf((float)g_deg[rr0]) : 0.f;
    float d1 = (rr1 < N_NODES) ? rsqrtf((float)g_deg[rr1]) : 0.f;
    #pragma unroll
    for (int j = 0; j < 4; j++) {
        int col = warp_c * 32 + j * 8 + 2 * kc;
        if (rr0 < N_NODES) {
            float2 v = make_float2(acc[j][0] * d0, acc[j][1] * d0);
            size_t idx = (size_t)rr0 * HID + col;
            *(float2*)&g_hs[idx]   = v;
            *(float2*)&g_acc1[idx] = v;   // self-loop contribution
        }
        if (rr1 < N_NODES) {
            float2 v = make_float2(acc[j][2] * d1, acc[j][3] * d1);
            size_t idx = (size_t)rr1 * HID + col;
            *(float2*)&g_hs[idx]   = v;
            *(float2*)&g_acc1[idx] = v;
        }
    }
}

// ---------------- scatter layer 1: acc1[tgt] += hs[src], 64 dims ----------------
__global__ void k_scatter1(const int* __restrict__ ei) {
    int tid = blockIdx.x * blockDim.x + threadIdx.x;   // E*16
    int e = tid >> 4, c = tid & 15;
    int s = clampN(__ldg(&ei[e]));
    int t = clampN(__ldg(&ei[E_EDGES + e]));
    float4 v = *(const float4*)&g_hs[(size_t)s * HID + c * 4];
    red_add_v4(&g_acc1[(size_t)t * HID + c * 4], v);
}

// ---------------- GEMM2 (3xTF32 tensor cores) ----------------
// zs = (relu(acc1*dinv + b1) @ W2) * dinv[row]; acc2 = zs
// tile 64 rows x 32 cols, K=64 resident, 8 warps = 4 row-groups x 2 col-groups;
// warp = 16 rows (1 m16) x 16 cols (2 n8). relu+bias fused into staging.
__global__ void __launch_bounds__(256)
k_gemm2(const float* __restrict__ W2, const float* __restrict__ b1) {
    __shared__ float    hs2[64][68];    // relu'd h1 tile; bank (4r+k)%32 conflict-free
    __shared__ unsigned wsh[64][40];    // tf32 hi of W2, [k][n]; bank (8k+n)%32
    __shared__ unsigned wsl[64][40];    // tf32 lo of W2
    int row0 = blockIdx.x * 64;
    int tid  = threadIdx.x;             // 256
    int warp = tid >> 5, lane = tid & 31;
    int warp_r = warp >> 1, warp_c = warp & 1;

    // stage h1 tile with fused relu: 64 rows x 16 float4 = 1024 float4, 4/thread
    #pragma unroll
    for (int i = 0; i < 4; i++) {
        int lin = tid + i * 256;
        int r = lin >> 4, k4 = lin & 15;
        float4 v = make_float4(0.f, 0.f, 0.f, 0.f);
        int row = row0 + r;
        if (row < N_NODES) {
            float d = rsqrtf((float)g_deg[row]);
            float4 a  = *(const float4*)&g_acc1[(size_t)row * HID + k4 * 4];
            float4 bb = *(const float4*)&b1[k4 * 4];
            v.x = fmaxf(a.x * d + bb.x, 0.f);
            v.y = fmaxf(a.y * d + bb.y, 0.f);
            v.z = fmaxf(a.z * d + bb.z, 0.f);
            v.w = fmaxf(a.w * d + bb.w, 0.f);
        }
        *(float4*)&hs2[r][k4 * 4] = v;
    }
    // stage + split W2: 64 k x 8 float4 = 512 float4, 2/thread
    #pragma unroll
    for (int i = 0; i < 2; i++) {
        int lin = tid + i * 256;
        int k = lin >> 3, c4 = lin & 7;
        float4 v = *(const float4*)&W2[(size_t)k * EMB + c4 * 4];
        unsigned h0, l0, h1, l1, h2, l2, h3, l3;
        split_tf32(v.x, h0, l0); split_tf32(v.y, h1, l1);
        split_tf32(v.z, h2, l2); split_tf32(v.w, h3, l3);
        wsh[k][c4 * 4 + 0] = h0; wsh[k][c4 * 4 + 1] = h1;
        wsh[k][c4 * 4 + 2] = h2; wsh[k][c4 * 4 + 3] = h3;
        wsl[k][c4 * 4 + 0] = l0; wsl[k][c4 * 4 + 1] = l1;
        wsl[k][c4 * 4 + 2] = l2; wsl[k][c4 * 4 + 3] = l3;
    }
    __syncthreads();

    float acc[2][4] = {};
    int q  = lane >> 2;        // 0..7
    int kc = lane & 3;         // 0..3
    int r0 = warp_r * 16 + q;

    #pragma unroll
    for (int k0 = 0; k0 < HID; k0 += 8) {
        unsigned ah[4], al[4];
        split_tf32(hs2[r0    ][k0 + kc    ], ah[0], al[0]);
        split_tf32(hs2[r0 + 8][k0 + kc    ], ah[1], al[1]);
        split_tf32(hs2[r0    ][k0 + kc + 4], ah[2], al[2]);
        split_tf32(hs2[r0 + 8][k0 + kc + 4], ah[3], al[3]);
        #pragma unroll
        for (int j = 0; j < 2; j++) {
            int col = warp_c * 16 + j * 8 + q;
            unsigned bh0 = wsh[k0 + kc    ][col];
            unsigned bh1 = wsh[k0 + kc + 4][col];
            unsigned bl0 = wsl[k0 + kc    ][col];
            unsigned bl1 = wsl[k0 + kc + 4][col];
            mma_tf32(acc[j], ah[0], ah[1], ah[2], ah[3], bh0, bh1);
            mma_tf32(acc[j], ah[0], ah[1], ah[2], ah[3], bl0, bl1);
            mma_tf32(acc[j], al[0], al[1], al[2], al[3], bh0, bh1);
        }
    }

    int rr0 = row0 + r0, rr1 = rr0 + 8;
    float d0 = (rr0 < N_NODES) ? rsqrtf((float)g_deg[rr0]) : 0.f;
    float d1 = (rr1 < N_NODES) ? rsqrtf((float)g_deg[rr1]) : 0.f;
    #pragma unroll
    for (int j = 0; j < 2; j++) {
        int col = warp_c * 16 + j * 8 + 2 * kc;
        if (rr0 < N_NODES) {
            float2 v = make_float2(acc[j][0] * d0, acc[j][1] * d0);
            size_t idx = (size_t)rr0 * EMB + col;
            *(float2*)&g_zs[idx]   = v;
            *(float2*)&g_acc2[idx] = v;   // self-loop contribution
        }
        if (rr1 < N_NODES) {
            float2 v = make_float2(acc[j][2] * d1, acc[j][3] * d1);
            size_t idx = (size_t)rr1 * EMB + col;
            *(float2*)&g_zs[idx]   = v;
            *(float2*)&g_acc2[idx] = v;
        }
    }
}

// ---------------- scatter layer 2: acc2[tgt] += zs[src], 32 dims ----------------
__global__ void k_scatter2(const int* __restrict__ ei) {
    int tid = blockIdx.x * blockDim.x + threadIdx.x;   // E*8
    int e = tid >> 3, c = tid & 7;
    int s = clampN(__ldg(&ei[e]));
    int t = clampN(__ldg(&ei[E_EDGES + e]));
    float4 v = *(const float4*)&g_zs[(size_t)s * EMB + c * 4];
    red_add_v4(&g_acc2[(size_t)t * EMB + c * 4], v);
}

// ---------------- final z: z = dinv*acc2 + b2 -> d_out ----------------
__global__ void k_z(const float* __restrict__ b2, float* __restrict__ z_out) {
    int idx = blockIdx.x * blockDim.x + threadIdx.x;   // N*8 float4s
    int row = idx >> 3, c = idx & 7;
    float d = rsqrtf((float)g_deg[row]);
    float4 a = *(const float4*)&g_acc2[(size_t)idx * 4];
    float4 bb = *(const float4*)&b2[c * 4];
    float4 o = make_float4(a.x * d + bb.x, a.y * d + bb.y, a.z * d + bb.z, a.w * d + bb.w);
    *(float4*)&z_out[(size_t)idx * 4] = o;
}

// ---------------- decode: recon[e] = dot(z[src], z[tgt]) ----------------
__global__ void k_decode(const int* __restrict__ ei,
                         const float* __restrict__ z, float* __restrict__ recon) {
    int tid = blockIdx.x * blockDim.x + threadIdx.x;   // E*8
    int e = tid >> 3, c = tid & 7;
    int s = clampN(__ldg(&ei[e]));
    int t = clampN(__ldg(&ei[E_EDGES + e]));
    float4 a = *(const float4*)&z[(size_t)s * EMB + c * 4];
    float4 b = *(const float4*)&z[(size_t)t * EMB + c * 4];
    float p = a.x * b.x + a.y * b.y + a.z * b.z + a.w * b.w;
    p += __shfl_down_sync(0xffffffffu, p, 4);
    p += __shfl_down_sync(0xffffffffu, p, 2);
    p += __shfl_down_sync(0xffffffffu, p, 1);
    if (c == 0) recon[e] = p;
}

// ---------------- launch ----------------
extern "C" void kernel_launch(void* const* d_in, const int* in_sizes, int n_in,
                              void* d_out, int out_size) {
    const float* x  = (const float*)d_in[0];
    const float* W1 = (const float*)d_in[1];
    const float* b1 = (const float*)d_in[2];
    const float* W2 = (const float*)d_in[3];
    const float* b2 = (const float*)d_in[4];
    const int*   ei = (const int*)d_in[5];
    float* z_out = (float*)d_out;                          // N*EMB
    float* recon = (float*)d_out + (size_t)N_NODES * EMB;  // E

    k_init_deg<<<(N_NODES + 255) / 256, 256>>>();
    k_edges<<<E_EDGES / 256, 256>>>(ei);

    k_gemm1<<<(N_NODES + 63) / 64, 256>>>(x, W1);
    k_scatter1<<<(E_EDGES * 16) / 256, 256>>>(ei);

    k_gemm2<<<(N_NODES + 63) / 64, 256>>>(W2, b1);
    k_scatter2<<<(E_EDGES * 8) / 256, 256>>>(ei);
    k_z<<<(N_NODES * 8) / 256, 256>>>(b2, z_out);

    k_decode<<<(E_EDGES * 8) / 256, 256>>>(ei, z_out, recon);
}

// round 16
// speedup vs baseline: 1.1221x; 1.0882x over previous
#include <cuda_runtime.h>

#define N_NODES 100000
#define E_EDGES 1600000
#define IN_DIMC 128
#define HID 64
#define EMB 32

// ---------------- device scratch (no allocations allowed) ----------------
__device__ int   g_deg[N_NODES];
__device__ float g_hs  [(size_t)N_NODES * HID];  // (x@W1) * dinv[row]
__device__ float g_acc1[(size_t)N_NODES * HID];  // scatter accumulator L1
__device__ float g_zs  [(size_t)N_NODES * EMB];  // (h1@W2) * dinv[row]
__device__ float g_acc2[(size_t)N_NODES * EMB];  // scatter accumulator L2

// one-instruction 16B global f32 reduction (sm_90+)
__device__ __forceinline__ void red_add_v4(float* addr, float4 v) {
    asm volatile("red.global.add.v4.f32 [%0], {%1, %2, %3, %4};"
                 :: "l"(addr), "f"(v.x), "f"(v.y), "f"(v.z), "f"(v.w)
                 : "memory");
}

__device__ __forceinline__ int clampN(int v) {
    return ((unsigned)v >= N_NODES) ? 0 : v;   // defensive: rel_err not crash
}

// tf32 helpers
__device__ __forceinline__ unsigned tf32_of(float f) {
    unsigned r;
    asm("cvt.rna.tf32.f32 %0, %1;" : "=r"(r) : "f"(f));
    return r;
}
__device__ __forceinline__ void split_tf32(float f, unsigned& hi, unsigned& lo) {
    hi = tf32_of(f);
    lo = tf32_of(f - __uint_as_float(hi));
}

// tf32 tensor-core mma: D(16x8) += A(16x8) * B(8x8), A row-major, B col-major
__device__ __forceinline__ void mma_tf32(float* c,
                                         unsigned a0, unsigned a1, unsigned a2, unsigned a3,
                                         unsigned b0, unsigned b1) {
    asm volatile(
        "mma.sync.aligned.m16n8k8.row.col.f32.tf32.tf32.f32 "
        "{%0,%1,%2,%3}, {%4,%5,%6,%7}, {%8,%9}, {%0,%1,%2,%3};"
        : "+f"(c[0]), "+f"(c[1]), "+f"(c[2]), "+f"(c[3])
        : "r"(a0), "r"(a1), "r"(a2), "r"(a3), "r"(b0), "r"(b1));
}

// ---------------- degree prep ----------------
__global__ void k_init_deg() {
    int i = blockIdx.x * blockDim.x + threadIdx.x;
    if (i < N_NODES) g_deg[i] = 1;  // self-loop
}

__global__ void k_edges(const int* __restrict__ ei) {
    int i = blockIdx.x * blockDim.x + threadIdx.x;
    if (i < E_EDGES) {
        int t = clampN(ei[E_EDGES + i]);
        atomicAdd(&g_deg[t], 1);
    }
}

// ---------------- GEMM1 (3xTF32 tensor cores): hs = (x @ W1) * dinv; acc1 = hs ---
// tile 64 rows x 64 cols, K=128 resident, smem 105KB -> 2 CTAs/SM.
// 8 warps = 4 row-groups x 2 col-groups; warp = 16 rows (1 m16) x 32 cols (4 n8).
__global__ void __launch_bounds__(256, 2)
k_gemm1(const float* __restrict__ x, const float* __restrict__ W1) {
    __shared__ float    xs [64][132];   // [row][k]; bank (4r+k)%32 -> conflict-free
    __shared__ unsigned wsh[128][72];   // tf32 hi of W1, [k][n]; bank (8k+n)%32
    __shared__ unsigned wsl[128][72];   // tf32 lo of W1
    int row0 = blockIdx.x * 64;
    int tid  = threadIdx.x;             // 256
    int warp = tid >> 5, lane = tid & 31;
    int warp_r = warp >> 1, warp_c = warp & 1;

    // stage x tile: 64 rows x 32 float4 = 2048 float4, 8 per thread (coalesced)
    #pragma unroll
    for (int i = 0; i < 8; i++) {
        int lin = tid + i * 256;
        int r = lin >> 5, f4 = lin & 31;
        float4 v = make_float4(0.f, 0.f, 0.f, 0.f);
        int row = row0 + r;
        if (row < N_NODES)
            v = *(const float4*)&x[(size_t)row * IN_DIMC + f4 * 4];
        *(float4*)&xs[r][f4 * 4] = v;
    }
    // stage + split W1: 128 k x 16 float4 = 2048 float4, 8 per thread
    #pragma unroll
    for (int i = 0; i < 8; i++) {
        int lin = tid + i * 256;
        int k = lin >> 4, c4 = lin & 15;
        float4 v = *(const float4*)&W1[(size_t)k * HID + c4 * 4];
        unsigned h0, l0, h1, l1, h2, l2, h3, l3;
        split_tf32(v.x, h0, l0); split_tf32(v.y, h1, l1);
        split_tf32(v.z, h2, l2); split_tf32(v.w, h3, l3);
        wsh[k][c4 * 4 + 0] = h0; wsh[k][c4 * 4 + 1] = h1;
        wsh[k][c4 * 4 + 2] = h2; wsh[k][c4 * 4 + 3] = h3;
        wsl[k][c4 * 4 + 0] = l0; wsl[k][c4 * 4 + 1] = l1;
        wsl[k][c4 * 4 + 2] = l2; wsl[k][c4 * 4 + 3] = l3;
    }
    __syncthreads();

    float acc[4][4] = {};
    int q  = lane >> 2;        // 0..7
    int kc = lane & 3;         // 0..3
    int r0 = warp_r * 16 + q;  // fragment rows r0, r0+8

    #pragma unroll 4
    for (int k0 = 0; k0 < IN_DIMC; k0 += 8) {
        unsigned ah[4], al[4];
        split_tf32(xs[r0    ][k0 + kc    ], ah[0], al[0]);
        split_tf32(xs[r0 + 8][k0 + kc    ], ah[1], al[1]);
        split_tf32(xs[r0    ][k0 + kc + 4], ah[2], al[2]);
        split_tf32(xs[r0 + 8][k0 + kc + 4], ah[3], al[3]);
        #pragma unroll
        for (int j = 0; j < 4; j++) {
            int col = warp_c * 32 + j * 8 + q;
            unsigned bh0 = wsh[k0 + kc    ][col];
            unsigned bh1 = wsh[k0 + kc + 4][col];
            unsigned bl0 = wsl[k0 + kc    ][col];
            unsigned bl1 = wsl[k0 + kc + 4][col];
            mma_tf32(acc[j], ah[0], ah[1], ah[2], ah[3], bh0, bh1);
            mma_tf32(acc[j], ah[0], ah[1], ah[2], ah[3], bl0, bl1);
            mma_tf32(acc[j], al[0], al[1], al[2], al[3], bh0, bh1);
        }
    }

    // epilogue: lane (q,kc) of tile j holds rows (rr0, rr0+8), cols warp_c*32+j*8+2kc+{0,1}
    int rr0 = row0 + r0, rr1 = rr0 + 8;
    float d0 = (rr0 < N_NODES) ? rsqrtf((float)g_deg[rr0]) : 0.f;
    float d1 = (rr1 < N_NODES) ? rsqrtf((float)g_deg[rr1]) : 0.f;
    #pragma unroll
    for (int j = 0; j < 4; j++) {
        int col = warp_c * 32 + j * 8 + 2 * kc;
        if (rr0 < N_NODES) {
            float2 v = make_float2(acc[j][0] * d0, acc[j][1] * d0);
            size_t idx = (size_t)rr0 * HID + col;
            *(float2*)&g_hs[idx]   = v;
            *(float2*)&g_acc1[idx] = v;   // self-loop contribution
        }
        if (rr1 < N_NODES) {
            float2 v = make_float2(acc[j][2] * d1, acc[j][3] * d1);
            size_t idx = (size_t)rr1 * HID + col;
            *(float2*)&g_hs[idx]   = v;
            *(float2*)&g_acc1[idx] = v;
        }
    }
}

// ---------------- scatter layer 1: acc1[tgt] += hs[src], 64 dims ----------------
// 8 threads/edge, 2 independent float4 chains per thread (ILP=2)
__global__ void k_scatter1(const int* __restrict__ ei) {
    int tid = blockIdx.x * blockDim.x + threadIdx.x;   // E*8
    int e = tid >> 3, c = tid & 7;
    int s = clampN(__ldg(&ei[e]));
    int t = clampN(__ldg(&ei[E_EDGES + e]));
    const float4* src = (const float4*)&g_hs[(size_t)s * HID];
    float*        dst = &g_acc1[(size_t)t * HID];
    float4 v0 = __ldg(&src[c]);
    float4 v1 = __ldg(&src[c + 8]);
    red_add_v4(dst + c * 4, v0);
    red_add_v4(dst + (c + 8) * 4, v1);
}

// ---------------- GEMM2 (3xTF32 tensor cores) ----------------
// zs = (relu(acc1*dinv + b1) @ W2) * dinv[row]; acc2 = zs
// tile 64 rows x 32 cols, K=64 resident, 8 warps = 4 row-groups x 2 col-groups;
// warp = 16 rows (1 m16) x 16 cols (2 n8). relu+bias fused into staging.
__global__ void __launch_bounds__(256)
k_gemm2(const float* __restrict__ W2, const float* __restrict__ b1) {
    __shared__ float    hs2[64][68];    // relu'd h1 tile; bank (4r+k)%32 conflict-free
    __shared__ unsigned wsh[64][40];    // tf32 hi of W2, [k][n]; bank (8k+n)%32
    __shared__ unsigned wsl[64][40];    // tf32 lo of W2
    int row0 = blockIdx.x * 64;
    int tid  = threadIdx.x;             // 256
    int warp = tid >> 5, lane = tid & 31;
    int warp_r = warp >> 1, warp_c = warp & 1;

    // stage h1 tile with fused relu: 64 rows x 16 float4 = 1024 float4, 4/thread
    #pragma unroll
    for (int i = 0; i < 4; i++) {
        int lin = tid + i * 256;
        int r = lin >> 4, k4 = lin & 15;
        float4 v = make_float4(0.f, 0.f, 0.f, 0.f);
        int row = row0 + r;
        if (row < N_NODES) {
            float d = rsqrtf((float)g_deg[row]);
            float4 a  = *(const float4*)&g_acc1[(size_t)row * HID + k4 * 4];
            float4 bb = *(const float4*)&b1[k4 * 4];
            v.x = fmaxf(a.x * d + bb.x, 0.f);
            v.y = fmaxf(a.y * d + bb.y, 0.f);
            v.z = fmaxf(a.z * d + bb.z, 0.f);
            v.w = fmaxf(a.w * d + bb.w, 0.f);
        }
        *(float4*)&hs2[r][k4 * 4] = v;
    }
    // stage + split W2: 64 k x 8 float4 = 512 float4, 2/thread
    #pragma unroll
    for (int i = 0; i < 2; i++) {
        int lin = tid + i * 256;
        int k = lin >> 3, c4 = lin & 7;
        float4 v = *(const float4*)&W2[(size_t)k * EMB + c4 * 4];
        unsigned h0, l0, h1, l1, h2, l2, h3, l3;
        split_tf32(v.x, h0, l0); split_tf32(v.y, h1, l1);
        split_tf32(v.z, h2, l2); split_tf32(v.w, h3, l3);
        wsh[k][c4 * 4 + 0] = h0; wsh[k][c4 * 4 + 1] = h1;
        wsh[k][c4 * 4 + 2] = h2; wsh[k][c4 * 4 + 3] = h3;
        wsl[k][c4 * 4 + 0] = l0; wsl[k][c4 * 4 + 1] = l1;
        wsl[k][c4 * 4 + 2] = l2; wsl[k][c4 * 4 + 3] = l3;
    }
    __syncthreads();

    float acc[2][4] = {};
    int q  = lane >> 2;        // 0..7
    int kc = lane & 3;         // 0..3
    int r0 = warp_r * 16 + q;

    #pragma unroll
    for (int k0 = 0; k0 < HID; k0 += 8) {
        unsigned ah[4], al[4];
        split_tf32(hs2[r0    ][k0 + kc    ], ah[0], al[0]);
        split_tf32(hs2[r0 + 8][k0 + kc    ], ah[1], al[1]);
        split_tf32(hs2[r0    ][k0 + kc + 4], ah[2], al[2]);
        split_tf32(hs2[r0 + 8][k0 + kc + 4], ah[3], al[3]);
        #pragma unroll
        for (int j = 0; j < 2; j++) {
            int col = warp_c * 16 + j * 8 + q;
            unsigned bh0 = wsh[k0 + kc    ][col];
            unsigned bh1 = wsh[k0 + kc + 4][col];
            unsigned bl0 = wsl[k0 + kc    ][col];
            unsigned bl1 = wsl[k0 + kc + 4][col];
            mma_tf32(acc[j], ah[0], ah[1], ah[2], ah[3], bh0, bh1);
            mma_tf32(acc[j], ah[0], ah[1], ah[2], ah[3], bl0, bl1);
            mma_tf32(acc[j], al[0], al[1], al[2], al[3], bh0, bh1);
        }
    }

    int rr0 = row0 + r0, rr1 = rr0 + 8;
    float d0 = (rr0 < N_NODES) ? rsqrtf((float)g_deg[rr0]) : 0.f;
    float d1 = (rr1 < N_NODES) ? rsqrtf((float)g_deg[rr1]) : 0.f;
    #pragma unroll
    for (int j = 0; j < 2; j++) {
        int col = warp_c * 16 + j * 8 + 2 * kc;
        if (rr0 < N_NODES) {
            float2 v = make_float2(acc[j][0] * d0, acc[j][1] * d0);
            size_t idx = (size_t)rr0 * EMB + col;
            *(float2*)&g_zs[idx]   = v;
            *(float2*)&g_acc2[idx] = v;   // self-loop contribution
        }
        if (rr1 < N_NODES) {
            float2 v = make_float2(acc[j][2] * d1, acc[j][3] * d1);
            size_t idx = (size_t)rr1 * EMB + col;
            *(float2*)&g_zs[idx]   = v;
            *(float2*)&g_acc2[idx] = v;
        }
    }
}

// ---------------- scatter layer 2: acc2[tgt] += zs[src], 32 dims ----------------
// 4 threads/edge, 2 independent float4 chains per thread (ILP=2)
__global__ void k_scatter2(const int* __restrict__ ei) {
    int tid = blockIdx.x * blockDim.x + threadIdx.x;   // E*4
    int e = tid >> 2, c = tid & 3;
    int s = clampN(__ldg(&ei[e]));
    int t = clampN(__ldg(&ei[E_EDGES + e]));
    const float4* src = (const float4*)&g_zs[(size_t)s * EMB];
    float*        dst = &g_acc2[(size_t)t * EMB];
    float4 v0 = __ldg(&src[c]);
    float4 v1 = __ldg(&src[c + 4]);
    red_add_v4(dst + c * 4, v0);
    red_add_v4(dst + (c + 4) * 4, v1);
}

// ---------------- final z: z = dinv*acc2 + b2 -> d_out ----------------
__global__ void k_z(const float* __restrict__ b2, float* __restrict__ z_out) {
    int idx = blockIdx.x * blockDim.x + threadIdx.x;   // N*8 float4s
    int row = idx >> 3, c = idx & 7;
    float d = rsqrtf((float)g_deg[row]);
    float4 a = *(const float4*)&g_acc2[(size_t)idx * 4];
    float4 bb = *(const float4*)&b2[c * 4];
    float4 o = make_float4(a.x * d + bb.x, a.y * d + bb.y, a.z * d + bb.z, a.w * d + bb.w);
    *(float4*)&z_out[(size_t)idx * 4] = o;
}

// ---------------- decode: recon[e] = dot(z[src], z[tgt]) ----------------
// 4 threads/edge, 2 float4 per endpoint per thread (ILP=4 loads), 2 shfl levels
__global__ void k_decode(const int* __restrict__ ei,
                         const float* __restrict__ z, float* __restrict__ recon) {
    int tid = blockIdx.x * blockDim.x + threadIdx.x;   // E*4
    int e = tid >> 2, c = tid & 3;
    int s = clampN(__ldg(&ei[e]));
    int t = clampN(__ldg(&ei[E_EDGES + e]));
    const float4* zs = (const float4*)&z[(size_t)s * EMB];
    const float4* zt = (const float4*)&z[(size_t)t * EMB];
    float4 a0 = __ldg(&zs[c]);
    float4 a1 = __ldg(&zs[c + 4]);
    float4 b0 = __ldg(&zt[c]);
    float4 b1 = __ldg(&zt[c + 4]);
    float p = a0.x * b0.x + a0.y * b0.y + a0.z * b0.z + a0.w * b0.w
            + a1.x * b1.x + a1.y * b1.y + a1.z * b1.z + a1.w * b1.w;
    p += __shfl_down_sync(0xffffffffu, p, 2);
    p += __shfl_down_sync(0xffffffffu, p, 1);
    if (c == 0) recon[e] = p;
}

// ---------------- launch ----------------
extern "C" void kernel_launch(void* const* d_in, const int* in_sizes, int n_in,
                              void* d_out, int out_size) {
    const float* x  = (const float*)d_in[0];
    const float* W1 = (const float*)d_in[1];
    const float* b1 = (const float*)d_in[2];
    const float* W2 = (const float*)d_in[3];
    const float* b2 = (const float*)d_in[4];
    const int*   ei = (const int*)d_in[5];
    float* z_out = (float*)d_out;                          // N*EMB
    float* recon = (float*)d_out + (size_t)N_NODES * EMB;  // E

    k_init_deg<<<(N_NODES + 255) / 256, 256>>>();
    k_edges<<<E_EDGES / 256, 256>>>(ei);

    k_gemm1<<<(N_NODES + 63) / 64, 256>>>(x, W1);
    k_scatter1<<<(E_EDGES * 8) / 256, 256>>>(ei);

    k_gemm2<<<(N_NODES + 63) / 64, 256>>>(W2, b1);
    k_scatter2<<<(E_EDGES * 4) / 256, 256>>>(ei);
    k_z<<<(N_NODES * 8) / 256, 256>>>(b2, z_out);

    k_decode<<<(E_EDGES * 4) / 256, 256>>>(ei, z_out, recon);
}